// round 6
// baseline (speedup 1.0000x reference)
#include <cuda_runtime.h>

// Problem shape (fixed by the dataset): B=4, S=4096, D=2048, W=4
#define BV 4
#define SV 4096
#define DV 2048
#define TOK 64            // tokens per score block
#define NROWS (TOK + 3)   // 67 real rows (3-row causal halo)
#define NGRP 17           // 68 rows incl. 1 pad row, 4 rows/group
#define RSLOT 12          // ring slots (12 x 8KB = 96KB dynamic smem)

// Scratch (no allocations allowed) ------------------------------------------
__device__ float g_rinv[BV * SV];
__device__ int   g_mask[BV * SV];
__device__ int   g_src [BV * SV];

// Packed f32x2 helpers --------------------------------------------------------
typedef unsigned long long u64;
static __device__ __forceinline__ u64 pk(float lo, float hi) {
    u64 r; asm("mov.b64 %0,{%1,%2};" : "=l"(r) : "f"(lo), "f"(hi)); return r;
}
static __device__ __forceinline__ void upk(u64 v, float& lo, float& hi) {
    asm("mov.b64 {%0,%1},%2;" : "=f"(lo), "=f"(hi) : "l"(v));
}
static __device__ __forceinline__ u64 f2fma(u64 a, u64 b, u64 c) {
    u64 d; asm("fma.rn.f32x2 %0,%1,%2,%3;" : "=l"(d) : "l"(a), "l"(b), "l"(c)); return d;
}
static __device__ __forceinline__ u64 f2mul(u64 a, u64 b) {
    u64 d; asm("mul.rn.f32x2 %0,%1,%2;" : "=l"(d) : "l"(a), "l"(b)); return d;
}

// cp.async helpers ------------------------------------------------------------
static __device__ __forceinline__ void cpa16(unsigned dst, const void* src) {
    asm volatile("cp.async.ca.shared.global [%0], [%1], 16;"
                 :: "r"(dst), "l"(src));
}
static __device__ __forceinline__ void cpa_commit() {
    asm volatile("cp.async.commit_group;");
}
template <int N>
static __device__ __forceinline__ void cpa_wait() {
    asm volatile("cp.async.wait_group %0;" :: "n"(N));
}
static __device__ __forceinline__ void sts_zero16(unsigned dst) {
    asm volatile("st.shared.v4.b32 [%0],{%1,%1,%1,%1};" :: "r"(dst), "r"(0));
}

// K0: rinv[b,s] = rsqrt(mean(x^2)+eps). One warp per token, 16 front-batched
// LDG.128 per thread (deep MLP) -> pure DRAM-bound streaming reduction.
__global__ void __launch_bounds__(256) rinv_kernel(const float* __restrict__ x) {
    const int gw   = (blockIdx.x * blockDim.x + threadIdx.x) >> 5;
    const int lane = threadIdx.x & 31;
    const float4* xr = (const float4*)(x + (size_t)gw * DV);
    float s = 0.f;
#pragma unroll
    for (int i = 0; i < 16; i++) {
        float4 v = xr[lane + i * 32];
        s += v.x * v.x + v.y * v.y + v.z * v.z + v.w * v.w;
    }
#pragma unroll
    for (int o = 16; o > 0; o >>= 1) s += __shfl_xor_sync(0xffffffffu, s, o);
    if (lane == 0) g_rinv[gw] = rsqrtf(s * (1.f / DV) + 1e-5f);
}

// K1: BARRIER-FREE fused norm-scale + causal dwconv(W=4) + silu + (p1-p0)
// dot -> sign/token. rinv comes from g_rinv (broadcast LDG, L1-hot), so
// warps are fully independent: no __syncthreads in the main loop, no
// block reductions. Rows stream through a 12-slot cp.async ring; each
// thread copies and consumes only its own 32B.
__global__ void __launch_bounds__(256, 2) score_kernel(
    const float* __restrict__ x, const float* __restrict__ nw,
    const float* __restrict__ cw, const float* __restrict__ pw)
{
    extern __shared__ float4 ring[];    // [RSLOT][512] : 12 x 8KB
    __shared__ float spart[TOK][8];     // per-token score warp partials

    const int b    = blockIdx.y;
    const int s0   = blockIdx.x * TOK;
    const int tid  = threadIdx.x;
    const int lane = tid & 31, wid = tid >> 5;
    const int c0   = tid * 8;

    unsigned ring_u32;
    {
        unsigned long long g;
        asm("cvta.to.shared.u64 %0, %1;" : "=l"(g) : "l"(ring));
        ring_u32 = (unsigned)g + (unsigned)(tid * 32);
    }

    // Constants: fold nw into conv taps -> wnv[tap][c] = cw[c][tap]*nw[c]
    u64 wnv2[4][4];
    float gch[8];
#pragma unroll
    for (int j = 0; j < 4; j++) {
        int d = c0 + 2 * j;
        float n0 = nw[d], n1 = nw[d + 1];
#pragma unroll
        for (int wi = 0; wi < 4; wi++)
            wnv2[wi][j] = pk(cw[d * 4 + wi] * n0, cw[(d + 1) * 4 + wi] * n1);
    }
#pragma unroll
    for (int c = 0; c < 8; c++) gch[c] = pw[DV + c0 + c] - pw[c0 + c];

    u64 acc2[4][4];
#pragma unroll
    for (int s = 0; s < 4; s++)
#pragma unroll
        for (int j = 0; j < 4; j++) acc2[s][j] = 0ull;

    const float* xb = x + (size_t)b * SV * DV + c0;
    const float* rb = g_rinv + b * SV;

    // Stage rows 4g..4g+3 into the ring; one commit group per row-group.
    auto produce_group = [&](int g) {
        if (g < NGRP) {
#pragma unroll
            for (int k = 0; k < 4; k++) {
                const int i = 4 * g + k;
                const int r = s0 - 3 + i;
                const unsigned dst = ring_u32 + (unsigned)((i % RSLOT) * 8192);
                if (i < NROWS && r >= 0) {
                    const float* src = xb + (size_t)r * DV;
                    cpa16(dst, src);
                    cpa16(dst + 16, src + 4);
                } else {
                    sts_zero16(dst);
                    sts_zero16(dst + 16);
                }
            }
        }
        cpa_commit();   // empty commit keeps wait_group accounting uniform
    };

    produce_group(0);
    produce_group(1);

#pragma unroll 1
    for (int g = 0; g < NGRP; g++) {
        // rinv loads for this group (independent of ring; issue early).
        // Clamp r into range: for pad/negative rows the row data is zero,
        // so the rinv value is irrelevant but the address must be valid.
        float rv[4];
#pragma unroll
        for (int k = 0; k < 4; k++) {
            int r = s0 - 3 + 4 * g + k;
            r = (r < 0) ? 0 : ((r > SV - 1) ? SV - 1 : r);
            rv[k] = __ldg(rb + r);
        }

        cpa_wait<1>();   // groups 0..g landed (g+1 may be in flight)

        float4 a[4], q[4];
#pragma unroll
        for (int k = 0; k < 4; k++) {
            const int i = 4 * g + k;
            const float4* slot = &ring[(i % RSLOT) * 512 + tid * 2];
            a[k] = slot[0]; q[k] = slot[1];
        }
        produce_group(g + 2);

        // Conv accumulate + token completion (ring slots compile-time in k)
#pragma unroll
        for (int k = 0; k < 4; k++) {
            const int i = 4 * g + k;
            const u64 ri2 = pk(rv[k], rv[k]);
            u64 xr2[4] = { f2mul(ri2, pk(a[k].x, a[k].y)),
                           f2mul(ri2, pk(a[k].z, a[k].w)),
                           f2mul(ri2, pk(q[k].x, q[k].y)),
                           f2mul(ri2, pk(q[k].z, q[k].w)) };

#pragma unroll
            for (int jj = 0; jj < 4; jj++) {
                const int slot = (k + 1 + jj) & 3;
#pragma unroll
                for (int j = 0; j < 4; j++)
                    acc2[slot][j] = f2fma(wnv2[3 - jj][j], xr2[j], acc2[slot][j]);
            }

            if (i >= 3 && i < NROWS) {
                const int slot = (k + 1) & 3;
                float p = 0.f;
#pragma unroll
                for (int j = 0; j < 4; j++) {
                    float v0, v1; upk(acc2[slot][j], v0, v1);
                    p += gch[2 * j]     * __fdividef(v0, 1.f + __expf(-v0));
                    p += gch[2 * j + 1] * __fdividef(v1, 1.f + __expf(-v1));
                }
#pragma unroll
                for (int o = 16; o > 0; o >>= 1)
                    p += __shfl_xor_sync(0xffffffffu, p, o);
                if (lane == 0) spart[i - 3][wid] = p;
            }
            {   // recycle slot
                const int slot = (k + 1) & 3;
#pragma unroll
                for (int j = 0; j < 4; j++) acc2[slot][j] = 0ull;
            }
        }
    }
    __syncthreads();   // the ONLY block barrier: publish spart
    if (tid < TOK) {
        float t = 0.f;
#pragma unroll
        for (int w = 0; w < 8; w++) t += spart[tid][w];
        g_mask[b * SV + s0 + tid] = (t > 0.f) ? 1 : 0;
    }
}

// K2: per-batch inclusive scan of masks -> inverse map src[b][c-1] = s -------
__global__ void __launch_bounds__(1024) scan_kernel() {
    const int b   = blockIdx.x;
    const int tid = threadIdx.x;
    for (int j = tid; j < SV; j += 1024) g_src[b * SV + j] = -1;
    __syncthreads();

    int base = tid * 4;
    int m[4], pre[4];
    int sum = 0;
#pragma unroll
    for (int k = 0; k < 4; k++) {
        m[k] = g_mask[b * SV + base + k];
        sum += m[k];
        pre[k] = sum;
    }
    int lane = tid & 31, wid = tid >> 5;
    int v = sum;
#pragma unroll
    for (int o = 1; o < 32; o <<= 1) {
        int t = __shfl_up_sync(0xffffffffu, v, o);
        if (lane >= o) v += t;
    }
    __shared__ int wsum[32];
    if (lane == 31) wsum[wid] = v;
    __syncthreads();
    if (wid == 0) {
        int t = wsum[lane];
#pragma unroll
        for (int o = 1; o < 32; o <<= 1) {
            int u = __shfl_up_sync(0xffffffffu, t, o);
            if (lane >= o) t += u;
        }
        wsum[lane] = t;
    }
    __syncthreads();
    int offset = (wid > 0 ? wsum[wid - 1] : 0) + (v - sum);
#pragma unroll
    for (int k = 0; k < 4; k++) {
        if (m[k]) g_src[b * SV + offset + pre[k] - 1] = base + k;
    }
}

// K3: row-wise gather of x (selected, packed) or zero-fill -------------------
__global__ void __launch_bounds__(256) scatter_kernel(
    const float* __restrict__ x, float* __restrict__ out)
{
    const int row = blockIdx.x;              // 0 .. B*S-1
    const int b   = row >> 12;               // S = 4096
    const int s   = g_src[row];
    float4* o = (float4*)(out + (size_t)row * DV) + threadIdx.x;
    if (s >= 0) {
        const float4* xr =
            (const float4*)(x + ((size_t)(b << 12) + s) * DV) + threadIdx.x;
        float4 v0 = __ldcs(xr);
        float4 v1 = __ldcs(xr + 256);
        __stcs(o, v0);
        __stcs(o + 256, v1);
    } else {
        float4 z = make_float4(0.f, 0.f, 0.f, 0.f);
        __stcs(o, z);
        __stcs(o + 256, z);
    }
}

extern "C" void kernel_launch(void* const* d_in, const int* in_sizes, int n_in,
                              void* d_out, int out_size) {
    const float* x  = (const float*)d_in[0];  // [B,S,D]
    const float* nw = (const float*)d_in[1];  // [D]
    const float* cw = (const float*)d_in[2];  // [D,4]
    const float* pw = (const float*)d_in[3];  // [2,D]
    float* out = (float*)d_out;               // [B,S,D]

    const int ring_bytes = RSLOT * 8192;      // 96KB dynamic smem
    cudaFuncSetAttribute(score_kernel,
                         cudaFuncAttributeMaxDynamicSharedMemorySize,
                         ring_bytes);

    rinv_kernel<<<(BV * SV) / 8, 256>>>(x);
    dim3 g1(SV / TOK, BV);
    score_kernel<<<g1, 256, ring_bytes>>>(x, nw, cw, pw);
    scan_kernel<<<BV, 1024>>>();
    scatter_kernel<<<BV * SV, 256>>>(x, out);
}

// round 7
// speedup vs baseline: 1.1167x; 1.1167x over previous
#include <cuda_runtime.h>

// Problem shape (fixed by the dataset): B=4, S=4096, D=2048, W=4
#define BV 4
#define SV 4096
#define DV 2048
#define TOK 64            // tokens per score block
#define NROWS (TOK + 3)   // 67 real rows (3-row causal halo)
#define NGRP 17           // 68 rows incl. 1 pad row, 4 rows/group
#define RSLOT 12          // ring slots (12 x 8KB = 96KB dynamic smem)

// Scratch (no allocations allowed) ------------------------------------------
__device__ int g_mask[BV * SV];
__device__ int g_src [BV * SV];

// Packed f32x2 helpers --------------------------------------------------------
typedef unsigned long long u64;
static __device__ __forceinline__ u64 pk(float lo, float hi) {
    u64 r; asm("mov.b64 %0,{%1,%2};" : "=l"(r) : "f"(lo), "f"(hi)); return r;
}
static __device__ __forceinline__ void upk(u64 v, float& lo, float& hi) {
    asm("mov.b64 {%0,%1},%2;" : "=f"(lo), "=f"(hi) : "l"(v));
}
static __device__ __forceinline__ u64 f2fma(u64 a, u64 b, u64 c) {
    u64 d; asm("fma.rn.f32x2 %0,%1,%2,%3;" : "=l"(d) : "l"(a), "l"(b), "l"(c)); return d;
}
static __device__ __forceinline__ u64 f2mul(u64 a, u64 b) {
    u64 d; asm("mul.rn.f32x2 %0,%1,%2;" : "=l"(d) : "l"(a), "l"(b)); return d;
}

// cp.async helpers ------------------------------------------------------------
static __device__ __forceinline__ void cpa16(unsigned dst, const void* src) {
    asm volatile("cp.async.ca.shared.global [%0], [%1], 16;"
                 :: "r"(dst), "l"(src));
}
static __device__ __forceinline__ void cpa_commit() {
    asm volatile("cp.async.commit_group;");
}
template <int N>
static __device__ __forceinline__ void cpa_wait() {
    asm volatile("cp.async.wait_group %0;" :: "n"(N));
}
static __device__ __forceinline__ void sts_zero16(unsigned dst) {
    asm volatile("st.shared.v4.b32 [%0],{%1,%1,%1,%1};" :: "r"(dst), "r"(0));
}

// Sum of 4 silu-gated terms with ONE reciprocal:
//   sum_i a_i * v_i / d_i  ==  n / D  (pairwise combine), d_i = 1 + e^-v_i
static __device__ __forceinline__ float silu4(
    float v0, float v1, float v2, float v3,
    float g0, float g1, float g2, float g3)
{
    float d0 = 1.f + __expf(-v0);
    float d1 = 1.f + __expf(-v1);
    float d2 = 1.f + __expf(-v2);
    float d3 = 1.f + __expf(-v3);
    float a0 = g0 * v0, a1 = g1 * v1, a2 = g2 * v2, a3 = g3 * v3;
    float n01 = fmaf(a0, d1, a1 * d0);
    float n23 = fmaf(a2, d3, a3 * d2);
    float D01 = d0 * d1;
    float D23 = d2 * d3;
    float n = fmaf(n01, D23, n23 * D01);
    float D = D01 * D23;
    return __fdividef(n, D);   // 1 MUFU.RCP + mul
}

// K1: fused rmsnorm + causal dwconv(W=4) + silu + (p1-p0) dot -> sign/token.
// 256 threads, 8 ch/thread, 64 tokens/block. Rows stream through a 12-slot
// cp.async ring, processed in groups of 4 with ONE barrier per group
// (parity-buffered rinv partials). 4-way combined division cuts MUFU per
// row/thread from 16 to 10.
__global__ void __launch_bounds__(256, 2) score_kernel(
    const float* __restrict__ x, const float* __restrict__ nw,
    const float* __restrict__ cw, const float* __restrict__ pw)
{
    extern __shared__ float4 ring[];    // [RSLOT][512] : 12 x 8KB
    __shared__ float wpart[2][4][8];    // rinv warp partials (group parity)
    __shared__ float spart[TOK][8];     // per-token score warp partials

    const int b    = blockIdx.y;
    const int s0   = blockIdx.x * TOK;
    const int tid  = threadIdx.x;
    const int lane = tid & 31, wid = tid >> 5;
    const int c0   = tid * 8;

    unsigned ring_u32;
    {
        unsigned long long g;
        asm("cvta.to.shared.u64 %0, %1;" : "=l"(g) : "l"(ring));
        ring_u32 = (unsigned)g + (unsigned)(tid * 32);
    }

    // Constants: fold nw into conv taps -> wnv[tap][c] = cw[c][tap]*nw[c]
    u64 wnv2[4][4];
    float gch[8];
#pragma unroll
    for (int j = 0; j < 4; j++) {
        int d = c0 + 2 * j;
        float n0 = nw[d], n1 = nw[d + 1];
#pragma unroll
        for (int wi = 0; wi < 4; wi++)
            wnv2[wi][j] = pk(cw[d * 4 + wi] * n0, cw[(d + 1) * 4 + wi] * n1);
    }
#pragma unroll
    for (int c = 0; c < 8; c++) gch[c] = pw[DV + c0 + c] - pw[c0 + c];

    u64 acc2[4][4];
#pragma unroll
    for (int s = 0; s < 4; s++)
#pragma unroll
        for (int j = 0; j < 4; j++) acc2[s][j] = 0ull;

    const float* xb = x + (size_t)b * SV * DV + c0;

    // Stage rows 4g..4g+3 into the ring; one commit group per row-group.
    auto produce_group = [&](int g) {
        if (g < NGRP) {
#pragma unroll
            for (int k = 0; k < 4; k++) {
                const int i = 4 * g + k;
                const int r = s0 - 3 + i;
                const unsigned dst = ring_u32 + (unsigned)((i % RSLOT) * 8192);
                if (i < NROWS && r >= 0) {
                    const float* src = xb + (size_t)r * DV;
                    cpa16(dst, src);
                    cpa16(dst + 16, src + 4);
                } else {
                    sts_zero16(dst);
                    sts_zero16(dst + 16);
                }
            }
        }
        cpa_commit();   // empty commit keeps wait_group accounting uniform
    };

    produce_group(0);
    produce_group(1);

#pragma unroll 1
    for (int g = 0; g < NGRP; g++) {
        cpa_wait<1>();   // groups 0..g landed (g+1 may be in flight)

        // Pull the 4 rows into registers (own 32B -> no barrier needed)
        float4 a[4], q[4];
#pragma unroll
        for (int k = 0; k < 4; k++) {
            const int i = 4 * g + k;
            const float4* slot = &ring[(i % RSLOT) * 512 + tid * 2];
            a[k] = slot[0]; q[k] = slot[1];
        }
        produce_group(g + 2);

        // 4 parallel block reductions for rinv (one barrier per group)
        const int par = g & 1;
#pragma unroll
        for (int k = 0; k < 4; k++) {
            float s = a[k].x * a[k].x + a[k].y * a[k].y
                    + a[k].z * a[k].z + a[k].w * a[k].w
                    + q[k].x * q[k].x + q[k].y * q[k].y
                    + q[k].z * q[k].z + q[k].w * q[k].w;
#pragma unroll
            for (int o = 16; o > 0; o >>= 1)
                s += __shfl_xor_sync(0xffffffffu, s, o);
            if (lane == 0) wpart[par][k][wid] = s;
        }
        __syncthreads();

        float rinv[4];
#pragma unroll
        for (int k = 0; k < 4; k++) {
            float tot = 0.f;
#pragma unroll
            for (int w = 0; w < 8; w++) tot += wpart[par][k][w];
            rinv[k] = rsqrtf(tot * (1.f / DV) + 1e-5f);
        }

        // Conv accumulate + token completion (ring slots compile-time in k)
#pragma unroll
        for (int k = 0; k < 4; k++) {
            const int i = 4 * g + k;
            const u64 ri2 = pk(rinv[k], rinv[k]);
            u64 xr2[4] = { f2mul(ri2, pk(a[k].x, a[k].y)),
                           f2mul(ri2, pk(a[k].z, a[k].w)),
                           f2mul(ri2, pk(q[k].x, q[k].y)),
                           f2mul(ri2, pk(q[k].z, q[k].w)) };

#pragma unroll
            for (int jj = 0; jj < 4; jj++) {
                const int slot = (k + 1 + jj) & 3;
#pragma unroll
                for (int j = 0; j < 4; j++)
                    acc2[slot][j] = f2fma(wnv2[3 - jj][j], xr2[j], acc2[slot][j]);
            }

            if (i >= 3 && i < NROWS) {
                const int slot = (k + 1) & 3;
                float v0, v1, v2, v3, v4, v5, v6, v7;
                upk(acc2[slot][0], v0, v1);
                upk(acc2[slot][1], v2, v3);
                upk(acc2[slot][2], v4, v5);
                upk(acc2[slot][3], v6, v7);
                float p = silu4(v0, v1, v2, v3, gch[0], gch[1], gch[2], gch[3])
                        + silu4(v4, v5, v6, v7, gch[4], gch[5], gch[6], gch[7]);
#pragma unroll
                for (int o = 16; o > 0; o >>= 1)
                    p += __shfl_xor_sync(0xffffffffu, p, o);
                if (lane == 0) spart[i - 3][wid] = p;
            }
            {   // recycle slot
                const int slot = (k + 1) & 3;
#pragma unroll
                for (int j = 0; j < 4; j++) acc2[slot][j] = 0ull;
            }
        }
    }
    __syncthreads();
    if (tid < TOK) {
        float t = 0.f;
#pragma unroll
        for (int w = 0; w < 8; w++) t += spart[tid][w];
        g_mask[b * SV + s0 + tid] = (t > 0.f) ? 1 : 0;
    }
}

// K2: per-batch inclusive scan of masks -> inverse map src[b][c-1] = s -------
__global__ void __launch_bounds__(1024) scan_kernel() {
    const int b   = blockIdx.x;
    const int tid = threadIdx.x;
    for (int j = tid; j < SV; j += 1024) g_src[b * SV + j] = -1;
    __syncthreads();

    int base = tid * 4;
    int m[4], pre[4];
    int sum = 0;
#pragma unroll
    for (int k = 0; k < 4; k++) {
        m[k] = g_mask[b * SV + base + k];
        sum += m[k];
        pre[k] = sum;
    }
    int lane = tid & 31, wid = tid >> 5;
    int v = sum;
#pragma unroll
    for (int o = 1; o < 32; o <<= 1) {
        int t = __shfl_up_sync(0xffffffffu, v, o);
        if (lane >= o) v += t;
    }
    __shared__ int wsum[32];
    if (lane == 31) wsum[wid] = v;
    __syncthreads();
    if (wid == 0) {
        int t = wsum[lane];
#pragma unroll
        for (int o = 1; o < 32; o <<= 1) {
            int u = __shfl_up_sync(0xffffffffu, t, o);
            if (lane >= o) t += u;
        }
        wsum[lane] = t;
    }
    __syncthreads();
    int offset = (wid > 0 ? wsum[wid - 1] : 0) + (v - sum);
#pragma unroll
    for (int k = 0; k < 4; k++) {
        if (m[k]) g_src[b * SV + offset + pre[k] - 1] = base + k;
    }
}

// K3: row-wise gather of x (selected, packed) or zero-fill -------------------
__global__ void __launch_bounds__(256) scatter_kernel(
    const float* __restrict__ x, float* __restrict__ out)
{
    const int row = blockIdx.x;              // 0 .. B*S-1
    const int b   = row >> 12;               // S = 4096
    const int s   = g_src[row];
    float4* o = (float4*)(out + (size_t)row * DV) + threadIdx.x;
    if (s >= 0) {
        const float4* xr =
            (const float4*)(x + ((size_t)(b << 12) + s) * DV) + threadIdx.x;
        float4 v0 = __ldcs(xr);
        float4 v1 = __ldcs(xr + 256);
        __stcs(o, v0);
        __stcs(o + 256, v1);
    } else {
        float4 z = make_float4(0.f, 0.f, 0.f, 0.f);
        __stcs(o, z);
        __stcs(o + 256, z);
    }
}

extern "C" void kernel_launch(void* const* d_in, const int* in_sizes, int n_in,
                              void* d_out, int out_size) {
    const float* x  = (const float*)d_in[0];  // [B,S,D]
    const float* nw = (const float*)d_in[1];  // [D]
    const float* cw = (const float*)d_in[2];  // [D,4]
    const float* pw = (const float*)d_in[3];  // [2,D]
    float* out = (float*)d_out;               // [B,S,D]

    const int ring_bytes = RSLOT * 8192;      // 96KB dynamic smem
    cudaFuncSetAttribute(score_kernel,
                         cudaFuncAttributeMaxDynamicSharedMemorySize,
                         ring_bytes);
    // Opt in to the max smem carveout so 2 blocks (2 x ~98KB) can co-reside.
    cudaFuncSetAttribute(score_kernel,
                         cudaFuncAttributePreferredSharedMemoryCarveout, 100);

    dim3 g1(SV / TOK, BV);
    score_kernel<<<g1, 256, ring_bytes>>>(x, nw, cw, pw);
    scan_kernel<<<BV, 1024>>>();
    scatter_kernel<<<BV * SV, 256>>>(x, out);
}